// round 17
// baseline (speedup 1.0000x reference)
#include <cuda_runtime.h>
#include <cstddef>

// SpanRepresentation: out[b, s, :] = concat(x[b,start,:], x[b,end,:], wemb[wid,:])
// B=16, L=512, D=768, W=8, WD=64, NS=4068. Spans ordered by width 1..8, then start.
//
// R17: R12/R16 core (128 threads, 4-phase MLP-4 row copy, streaming stores) with
// 4 consecutive spans per CTA (NS = 4068 = 4*1017 exactly). Amortizes the
// per-row prologue (wid bucket + address setup + CTA launch) 4x — the only cost
// left that scales with rows instead of bytes (ALU 18%/FMA 11% in R16).
// Rows are independent -> ptxas overlaps next row's loads with current stores.

constexpr int B    = 16;
constexpr int L    = 512;
constexpr int D    = 768;
constexpr int WD   = 64;
constexpr int NS   = 4068;
constexpr int RPC  = 4;                  // rows (spans) per CTA; NS/RPC = 1017

constexpr int D4   = D / 4;              // 192
constexpr int WD4  = WD / 4;             // 16
constexpr int ROW4 = (2 * D + WD) / 4;   // 400

__device__ __forceinline__ int width_bucket(int s) {
    int wid = 0;
    wid += (s >= 512);
    wid += (s >= 1023);
    wid += (s >= 1533);
    wid += (s >= 2042);
    wid += (s >= 2550);
    wid += (s >= 3057);
    wid += (s >= 3563);
    return wid;
}

__global__ __launch_bounds__(128, 16)
void span_repr_kernel(const float4* __restrict__ x,      // [B, L, D/4]
                      const float4* __restrict__ wemb,   // [8, WD/4]
                      float4* __restrict__ out)          // [B*NS, ROW4]
{
    const int s0  = blockIdx.x * RPC;    // first span of this CTA
    const int b   = blockIdx.y;
    const int tid = threadIdx.x;

    const float4* __restrict__ xb = x + (size_t)b * L * D4;
    float4* __restrict__ o = out + ((size_t)b * NS + s0) * ROW4;

    #pragma unroll
    for (int r = 0; r < RPC; ++r) {
        const int s     = s0 + r;
        const int wid   = width_bucket(s);                    // block-uniform
        const int off   = 512 * wid - (wid * (wid - 1)) / 2;
        const int start = s - off;
        const int end   = start + wid;

        const float4* __restrict__ xs = xb + (size_t)start * D4;
        const float4* __restrict__ xe = xb + (size_t)end   * D4;
        const float4* __restrict__ wf = wemb + (size_t)wid * WD4;

        // issue all loads first (MLP 4 per row; rows independent -> deeper overlap)
        const float4 v0 = __ldg(&xs[tid]);                                 // [0,128)
        const float4 v1 = (tid < 64) ? __ldg(&xs[tid + 128])               // [128,256)
                                     : __ldg(&xe[tid + 128 - D4]);
        const float4 v2 = __ldg(&xe[tid + 256 - D4]);                      // [256,384)
        float4 v3;
        if (tid < WD4) v3 = __ldg(&wf[tid]);                               // [384,400)

        // store burst (streaming: output touched once; keep x in L2)
        __stcs(&o[tid],        v0);
        __stcs(&o[tid + 128],  v1);
        __stcs(&o[tid + 256],  v2);
        if (tid < WD4) __stcs(&o[tid + 384], v3);

        o += ROW4;   // next consecutive output row
    }
}

extern "C" void kernel_launch(void* const* d_in, const int* in_sizes, int n_in,
                              void* d_out, int out_size)
{
    const float4* x    = (const float4*)d_in[0];   // [16, 512, 768] fp32
    const float4* wemb = (const float4*)d_in[1];   // [8, 64] fp32
    float4* out        = (float4*)d_out;           // [16, 4068, 1600] fp32

    (void)in_sizes; (void)n_in; (void)out_size;

    dim3 grid(NS / RPC, B);   // 1017 x 16 = 16272 CTAs, 4 rows each
    dim3 block(128);
    span_repr_kernel<<<grid, block>>>(x, wemb, out);
}